// round 5
// baseline (speedup 1.0000x reference)
#include <cuda_runtime.h>
#include <cuda_bf16.h>
#include <math.h>
#include <stdint.h>

// Problem constants
#define BS 4096
#define HL 20
#define NF 128
#define EF 128
#define TF 128
#define DM 640          // 3*NF + EF + TF
#define DIN 512         // DM - TF
#define NHEAD 2
#define DH 320          // DM / NHEAD
#define ODE_STEPS 8

// ---------------- scratch (device globals; no allocation allowed) ----------
__device__ float g_full [(size_t)BS*HL*DM];     // full_vals (tf32-rounded)
__device__ float g_nb   [(size_t)BS*HL*384];    // nb (tf32-rounded)
__device__ float g_kv   [(size_t)BS*HL*1280];   // k|v
__device__ float g_lef  [(size_t)BS*DIN];       // last_event_feat (tf32-rounded)
__device__ float g_qlast[(size_t)BS*DM];
__device__ float g_ctx  [(size_t)BS*DM];        // (tf32-rounded)
__device__ float g_qh   [(size_t)BS*NF];
__device__ float g_khv  [(size_t)BS*HL*256];    // kh|vh fused
__device__ float g_gi   [(size_t)BS*384];
__device__ float g_hpr  [(size_t)BS*NF];
__device__ float g_odewT[NF*NF];
__device__ float g_ipw  [1920*640];             // tf32-rounded in_proj_w
__device__ float g_gwih [384*512];              // tf32-rounded gru_w_ih
__device__ float g_wkvT [256*384];              // [attn_wk|attn_wv]^T (tf32)
__device__ float g_wq2  [128*640];              // outfn_w @ out_proj_w
__device__ float g_w3t  [128*640];              // fused qh weight (tf32)
__device__ float g_bqh  [128];                  // fused qh bias

__device__ __forceinline__ uint32_t f2tf(float x) {
    uint32_t u; asm("cvt.rna.tf32.f32 %0, %1;" : "=r"(u) : "f"(x)); return u;
}
__device__ __forceinline__ float tfr(float x) { return __uint_as_float(f2tf(x)); }

__device__ __forceinline__ void cp16(uint32_t dst, const void* src) {
    asm volatile("cp.async.cg.shared.global [%0], [%1], 16;" :: "r"(dst), "l"(src));
}

// ---------------- TF32 mma.sync GEMM, TN form --------------------------------
// C[M,N] = A[M,K] * B[N,K]^T + bias.  M%128==0, N%128==0, K%16==0.
// grid = (N/128, M/128), 128 threads, 4 warps of 64x64.
__global__ __launch_bounds__(128, 2)
void tgemm(int K, const float* __restrict__ A, int lda,
           const float* __restrict__ B,
           float* __restrict__ C, int ldc,
           const float* __restrict__ bias)
{
    __shared__ float As[2][128][20];
    __shared__ float Bs[2][128][20];
    int tid = threadIdx.x;
    int warp = tid >> 5, lane = tid & 31;
    int row0 = blockIdx.y * 128, col0 = blockIdx.x * 128;
    int m0 = (warp >> 1) * 64, n0 = (warp & 1) * 64;
    int g = lane >> 2, t = lane & 3;

    float c[4][8][4];
#pragma unroll
    for (int mi = 0; mi < 4; mi++)
#pragma unroll
        for (int ni = 0; ni < 8; ni++)
#pragma unroll
            for (int i = 0; i < 4; i++) c[mi][ni][i] = 0.f;

    const float* Ap = A + (size_t)row0 * lda;
    const float* Bp = B + (size_t)col0 * K;

    uint32_t sA = (uint32_t)__cvta_generic_to_shared(&As[0][0][0]);
    uint32_t sB = (uint32_t)__cvta_generic_to_shared(&Bs[0][0][0]);
    const uint32_t stg = 128u*20u*4u;

#define LOADSTAGE(s, kt) {                                                    \
        _Pragma("unroll")                                                     \
        for (int i = 0; i < 4; i++) {                                         \
            int j = tid + i*128, r = j >> 2, q = j & 3;                       \
            cp16(sA + (s)*stg + (uint32_t)(r*20 + q*4)*4u,                    \
                 Ap + (size_t)r*lda + (kt)*16 + q*4);                         \
            cp16(sB + (s)*stg + (uint32_t)(r*20 + q*4)*4u,                    \
                 Bp + (size_t)r*K + (kt)*16 + q*4);                           \
        }                                                                     \
        asm volatile("cp.async.commit_group;" ::: "memory");                  \
    }

    int T = K >> 4;
    LOADSTAGE(0, 0);

    for (int kt = 0; kt < T; kt++) {
        int s = kt & 1;
        asm volatile("cp.async.wait_group 0;" ::: "memory");
        __syncthreads();
        if (kt + 1 < T) LOADSTAGE(s ^ 1, kt + 1);
#pragma unroll
        for (int ks = 0; ks < 16; ks += 8) {
            uint32_t a[4][4], b[8][2];
#pragma unroll
            for (int mi = 0; mi < 4; mi++) {
                int rm = m0 + mi*16 + g;
                a[mi][0] = __float_as_uint(As[s][rm    ][ks + t    ]);
                a[mi][1] = __float_as_uint(As[s][rm + 8][ks + t    ]);
                a[mi][2] = __float_as_uint(As[s][rm    ][ks + t + 4]);
                a[mi][3] = __float_as_uint(As[s][rm + 8][ks + t + 4]);
            }
#pragma unroll
            for (int ni = 0; ni < 8; ni++) {
                int cn = n0 + ni*8 + g;
                b[ni][0] = __float_as_uint(Bs[s][cn][ks + t    ]);
                b[ni][1] = __float_as_uint(Bs[s][cn][ks + t + 4]);
            }
#pragma unroll
            for (int mi = 0; mi < 4; mi++)
#pragma unroll
                for (int ni = 0; ni < 8; ni++) {
                    asm volatile(
                        "mma.sync.aligned.m16n8k8.row.col.f32.tf32.tf32.f32 "
                        "{%0,%1,%2,%3},{%4,%5,%6,%7},{%8,%9},{%0,%1,%2,%3};\n"
                        : "+f"(c[mi][ni][0]), "+f"(c[mi][ni][1]),
                          "+f"(c[mi][ni][2]), "+f"(c[mi][ni][3])
                        : "r"(a[mi][0]), "r"(a[mi][1]), "r"(a[mi][2]), "r"(a[mi][3]),
                          "r"(b[ni][0]), "r"(b[ni][1]));
                }
        }
        __syncthreads();
    }

#pragma unroll
    for (int mi = 0; mi < 4; mi++) {
        size_t r1 = (size_t)(row0 + m0 + mi*16 + g);
        size_t r2 = r1 + 8;
#pragma unroll
        for (int ni = 0; ni < 8; ni++) {
            int cc = col0 + n0 + ni*8 + 2*t;
            float b0 = 0.f, b1 = 0.f;
            if (bias) { b0 = bias[cc]; b1 = bias[cc + 1]; }
            *(float2*)&C[r1*ldc + cc] = make_float2(c[mi][ni][0] + b0, c[mi][ni][1] + b1);
            *(float2*)&C[r2*ldc + cc] = make_float2(c[mi][ni][2] + b0, c[mi][ni][3] + b1);
        }
    }
#undef LOADSTAGE
}

// ---------------- build full_vals, nb, last_event_feat (tf32-rounded) ------
__global__ void build_kernel(const int* __restrict__ nids,
                             const int* __restrict__ hist_nids,
                             const int* __restrict__ aids,
                             const int* __restrict__ eids,
                             const float* __restrict__ hist_ts,
                             const int* __restrict__ dirs,
                             const float* __restrict__ node_feat,
                             const float* __restrict__ edge_feat,
                             const float* __restrict__ anony,
                             const float* __restrict__ tw,
                             const float* __restrict__ tb)
{
    int bl = blockIdx.x;            // b*HL + l
    int b  = bl / HL, l = bl % HL;
    int j  = threadIdx.x;           // 0..127
    int hn  = hist_nids[bl];
    int dir = dirs[bl];
    int nid = nids[b];
    int src = dir ? nid : hn;
    int dst = dir ? hn  : nid;
    float sv = tfr(node_feat[(size_t)src*NF + j]);
    float dv = tfr(node_feat[(size_t)dst*NF + j]);
    float av = tfr(anony[(size_t)aids[bl]*NF + j]);
    float ev = tfr(edge_feat[(size_t)eids[bl]*EF + j]);
    float dt = hist_ts[b*HL + HL-1] - hist_ts[bl];
    float tv = tfr(cosf(dt*tw[j] + tb[j]));

    float* fv = g_full + (size_t)bl*DM;
    if (l == HL-1) {
        float* lef = g_lef + (size_t)b*DIN;
        lef[j] = sv; lef[NF+j] = dv; lef[2*NF+j] = av; lef[3*NF+j] = ev;
        fv[j] = 0.f; fv[NF+j] = 0.f; fv[2*NF+j] = 0.f; fv[3*NF+j] = 0.f;
        fv[4*NF+j] = tv;
    } else {
        fv[j] = sv; fv[NF+j] = dv; fv[2*NF+j] = av; fv[3*NF+j] = ev;
        fv[4*NF+j] = tv;
    }
    float* nb = g_nb + (size_t)bl*384;
    nb[j]        = tfr(node_feat[(size_t)hn*NF + j]);
    nb[NF + j]   = ev;
    nb[2*NF + j] = tv;
}

__global__ void transpose_odew(const float* __restrict__ w)
{
    int idx = blockIdx.x*128 + threadIdx.x;
    int j = idx >> 7, k = idx & 127;
    g_odewT[k*NF + j] = w[idx];
}

__global__ void pack_wkvT(const float* __restrict__ wk, const float* __restrict__ wv)
{
    int idx = blockIdx.x*128 + threadIdx.x;   // 384*128
    int k = idx >> 7, n = idx & 127;
    g_wkvT[(size_t)n*384 + k]         = tfr(wk[idx]);
    g_wkvT[(size_t)(128 + n)*384 + k] = tfr(wv[idx]);
}

__global__ void cvt_tf32(const float* __restrict__ s, float* __restrict__ d, int n)
{
    int i = blockIdx.x*256 + threadIdx.x;
    if (i < n) d[i] = tfr(s[i]);
}

// W3 precompute: Wq2 = outfn_w @ out_proj_w  ([128,640])
__global__ void w3_step1(const float* __restrict__ outfn_w, const float* __restrict__ opw)
{
    __shared__ float srow[8][640];
    int i0 = blockIdx.x * 8;    // grid 16
    for (int j = threadIdx.x; j < 8*640; j += 128)
        srow[j/640][j%640] = outfn_w[(size_t)(i0 + j/640)*640 + (j%640)];
    __syncthreads();
    for (int t = 0; t < 5; t++) {
        int d = threadIdx.x + t*128;
        float acc[8] = {0,0,0,0,0,0,0,0};
        for (int k = 0; k < 640; k++) {
            float w = opw[(size_t)k*640 + d];
#pragma unroll
            for (int r = 0; r < 8; r++) acc[r] += srow[r][k]*w;
        }
        for (int r = 0; r < 8; r++) g_wq2[(size_t)(i0+r)*640 + d] = acc[r];
    }
}
// W3t[j,d] = sum_i Wq2[i,d] * attn_wq[i,j]   ([128,640], tf32-rounded)
__global__ void w3_step2(const float* __restrict__ attn_wq)
{
    __shared__ float wqc[8][128];
    int j0 = blockIdx.x * 8;    // grid 16
    for (int idx = threadIdx.x; idx < 8*128; idx += 128) {
        int r = idx >> 7, i = idx & 127;
        wqc[r][i] = attn_wq[(size_t)i*128 + j0 + r];
    }
    __syncthreads();
    for (int t = 0; t < 5; t++) {
        int d = threadIdx.x + t*128;
        float acc[8] = {0,0,0,0,0,0,0,0};
        for (int i = 0; i < 128; i++) {
            float w = g_wq2[(size_t)i*640 + d];
#pragma unroll
            for (int r = 0; r < 8; r++) acc[r] += wqc[r][i]*w;
        }
        for (int r = 0; r < 8; r++) g_w3t[(size_t)(j0+r)*640 + d] = tfr(acc[r]);
    }
}
// bqh[j] = sum_i (outfn_b[i] + sum_k out_proj_b[k]*outfn_w[i,k]) * attn_wq[i,j]
__global__ void w3_bias(const float* __restrict__ opb, const float* __restrict__ outfn_w,
                        const float* __restrict__ outfn_b, const float* __restrict__ attn_wq)
{
    __shared__ float bq2[128];
    int i = threadIdx.x;
    float a = outfn_b[i];
    for (int k = 0; k < 640; k++) a += opb[k]*outfn_w[(size_t)i*640 + k];
    bq2[i] = a;
    __syncthreads();
    float s = 0.f;
    for (int ii = 0; ii < 128; ii++) s += bq2[ii]*attn_wq[(size_t)ii*128 + i];
    g_bqh[i] = s;
}

// ---------------- attention 1 (query = last position) ----------------------
__global__ void attn1_kernel(const int* __restrict__ hist_nids)
{
    int b = blockIdx.x, tid = threadIdx.x;   // 256 threads
    __shared__ float sq[DM];
    __shared__ float sS[NHEAD*HL];
    __shared__ float sA[NHEAD*HL];
    for (int d = tid; d < DM; d += 256) sq[d] = g_qlast[(size_t)b*DM + d];
    __syncthreads();

    int warp = tid >> 5, lane = tid & 31;
    for (int p = warp; p < NHEAD*HL; p += 8) {
        int h = p / HL, m = p % HL;
        const float* krow = g_kv + (size_t)(b*HL + m)*1280 + h*DH;
        const float* qrow = sq + h*DH;
        float s = 0.f;
#pragma unroll
        for (int i = 0; i < 10; i++) { int d = lane + i*32; s += qrow[d]*krow[d]; }
#pragma unroll
        for (int o = 16; o; o >>= 1) s += __shfl_xor_sync(0xffffffffu, s, o);
        if (!lane) sS[p] = s * 0.05590169943749474f;   // 1/sqrt(320)
    }
    __syncthreads();
    if (tid < NHEAD) {
        int h = tid;
        float sc[HL], mx = -1e30f;
        for (int m = 0; m < HL; m++) {
            float v = sS[h*HL + m];
            if (hist_nids[b*HL + m] == 0 && m != HL-1) v = -1e9f;
            sc[m] = v; mx = fmaxf(mx, v);
        }
        float sum = 0.f;
        for (int m = 0; m < HL; m++) { float e = expf(sc[m]-mx); sc[m] = e; sum += e; }
        float inv = 1.f/sum;
        for (int m = 0; m < HL; m++) sA[h*HL + m] = sc[m]*inv;
    }
    __syncthreads();
    for (int d = tid; d < DM; d += 256) {
        int h = d / DH;
        const float* vbase = g_kv + (size_t)b*HL*1280 + 640 + d;
        float accv = 0.f;
#pragma unroll
        for (int m = 0; m < HL; m++) accv += sA[h*HL + m] * vbase[(size_t)m*1280];
        g_ctx[(size_t)b*DM + d] = tfr(accv);   // feeds qh GEMM
    }
}

// ---------------- attention 2 + merge + GRU ---------------------------------
__global__ void attn2_gru_kernel(const int* __restrict__ nids,
                                 const int* __restrict__ hist_nids,
                                 const float* __restrict__ hist_ts,
                                 const float* __restrict__ node_feat,
                                 const float* __restrict__ merge_w,
                                 const float* __restrict__ merge_b,
                                 const float* __restrict__ gwhh,
                                 const float* __restrict__ gbhh,
                                 float* __restrict__ out)
{
    int b = blockIdx.x, tid = threadIdx.x;   // 128 threads
    __shared__ float sqh[NF], ssc[HL], sa[HL], scat[2*NF], shpl[NF];
    sqh[tid] = g_qh[(size_t)b*NF + tid];
    __syncthreads();
    int warp = tid >> 5, lane = tid & 31;
    for (int l = warp; l < HL; l += 4) {
        const float* kr = g_khv + (size_t)(b*HL + l)*256;
        float s = 0.f;
#pragma unroll
        for (int i = 0; i < 4; i++) { int d = lane + i*32; s += sqh[d]*kr[d]; }
#pragma unroll
        for (int o = 16; o; o >>= 1) s += __shfl_xor_sync(0xffffffffu, s, o);
        if (!lane) ssc[l] = s * 0.08838834764831845f;  // 1/sqrt(128)
    }
    __syncthreads();
    if (tid == 0) {
        float sc[HL], mx = -1e30f;
        for (int l = 0; l < HL; l++) {
            float v = ssc[l];
            if (hist_nids[b*HL + l] == 0 && l != HL-1) v = -1e9f;
            sc[l] = v; mx = fmaxf(mx, v);
        }
        float sum = 0.f;
        for (int l = 0; l < HL; l++) { float e = expf(sc[l]-mx); sc[l] = e; sum += e; }
        float inv = 1.f/sum;
        for (int l = 0; l < HL; l++) sa[l] = sc[l]*inv;
    }
    __syncthreads();
    float c2 = 0.f;
#pragma unroll
    for (int l = 0; l < HL; l++) c2 += sa[l] * g_khv[(size_t)(b*HL + l)*256 + 128 + tid];
    scat[tid]      = c2;
    scat[NF + tid] = node_feat[(size_t)nids[b]*NF + tid];
    __syncthreads();

    float acc = merge_b[tid];
#pragma unroll 8
    for (int k = 0; k < 2*NF; k++) acc = fmaf(scat[k], merge_w[k*NF + tid], acc);
    float hpl = tanhf(acc);
    shpl[tid] = hpl;
    __syncthreads();

    float gh[3];
#pragma unroll
    for (int c = 0; c < 3; c++) {
        int i = c*NF + tid;
        float a = gbhh[i];
        const float* wrow = gwhh + (size_t)i*NF;
#pragma unroll 8
        for (int k = 0; k < NF; k++) a = fmaf(shpl[k], wrow[k], a);
        gh[c] = a;
    }
    const float* gi = g_gi + (size_t)b*384;
    float r = 1.f/(1.f + expf(-(gi[tid]       + gh[0])));
    float z = 1.f/(1.f + expf(-(gi[NF + tid]  + gh[1])));
    float n = tanhf(gi[2*NF + tid] + r*gh[2]);
    float hpr = (1.f - z)*n + z*hpl;
    g_hpr[(size_t)b*NF + tid] = hpr;
    out[(size_t)BS*NF + (size_t)b*NF + tid] = hpr;        // h_right
    if (tid == 0) out[(size_t)2*BS*NF + b] = hist_ts[b*HL + HL-1];
}

// ---------------- ODE (RK4, 8 steps) ----------------------------------------
__global__ void ode_kernel(const float* __restrict__ hist_ts,
                           const float* __restrict__ tnw,
                           const float* __restrict__ tnb,
                           const float* __restrict__ odeb,
                           float* __restrict__ out)
{
    int b = blockIdx.x, j = threadIdx.x;  // 128 threads
    __shared__ float y[NF];
    float t0 = hist_ts[b*HL + HL-2];
    float t1 = hist_ts[b*HL + HL-1];
    float ratio = t1 - t0;
    float z = g_hpr[(size_t)b*NF + j];
    float tw = tnw[j], tb = tnb[j], ob = odeb[j];
    const float ds = 1.f/ODE_STEPS;

    auto fstage = [&](float s, float zj) -> float {
        float te = cosf((s*ratio + t0)*tw + tb);
        __syncthreads();
        y[j] = zj + te;
        __syncthreads();
        float acc = ob;
        const float* wc = g_odewT + j;
#pragma unroll 8
        for (int k = 0; k < NF; k++) acc = fmaf(y[k], wc[k*NF], acc);
        return tanhf(acc) * ratio;
    };

    for (int i = 0; i < ODE_STEPS; i++) {
        float s = i * ds;
        float k1 = fstage(s,            z);
        float k2 = fstage(s + 0.5f*ds,  z + 0.5f*ds*k1);
        float k3 = fstage(s + 0.5f*ds,  z + 0.5f*ds*k2);
        float k4 = fstage(s + ds,       z + ds*k3);
        z += ds/6.f * (k1 + 2.f*k2 + 2.f*k3 + k4);
    }
    out[(size_t)b*NF + j] = z;   // h_left (invalid_rows provably always false)
}

// ---------------- host ------------------------------------------------------
extern "C" void kernel_launch(void* const* d_in, const int* in_sizes, int n_in,
                              void* d_out, int out_size)
{
    const int*   nids       = (const int*)  d_in[0];
    const int*   hist_nids  = (const int*)  d_in[2];
    const int*   aids       = (const int*)  d_in[3];
    const int*   eids       = (const int*)  d_in[4];
    const float* hist_ts    = (const float*)d_in[5];
    const int*   dirs       = (const int*)  d_in[6];
    const float* node_feat  = (const float*)d_in[7];
    const float* edge_feat  = (const float*)d_in[8];
    const float* anony_emb  = (const float*)d_in[9];
    const float* time_w     = (const float*)d_in[10];
    const float* time_b     = (const float*)d_in[11];
    const float* in_proj_w  = (const float*)d_in[12];
    const float* in_proj_b  = (const float*)d_in[13];
    const float* out_proj_w = (const float*)d_in[14];
    const float* out_proj_b = (const float*)d_in[15];
    const float* outfn_w    = (const float*)d_in[16];
    const float* outfn_b    = (const float*)d_in[17];
    const float* attn_wq    = (const float*)d_in[18];
    const float* attn_wk    = (const float*)d_in[19];
    const float* attn_wv    = (const float*)d_in[20];
    const float* merge_w    = (const float*)d_in[21];
    const float* merge_b    = (const float*)d_in[22];
    const float* gru_w_ih   = (const float*)d_in[23];
    const float* gru_w_hh   = (const float*)d_in[24];
    const float* gru_b_ih   = (const float*)d_in[25];
    const float* gru_b_hh   = (const float*)d_in[26];
    const float* ode_w      = (const float*)d_in[27];
    const float* ode_b      = (const float*)d_in[28];
    const float* tnode_w    = (const float*)d_in[29];
    const float* tnode_b    = (const float*)d_in[30];

    float* out = (float*)d_out;

    float *p_full, *p_kv, *p_lef, *p_qlast, *p_ctx, *p_qh, *p_khv, *p_nb,
          *p_gi, *p_ipw, *p_gwih, *p_wkvT, *p_w3t, *p_bqh;
    cudaGetSymbolAddress((void**)&p_full,  g_full);
    cudaGetSymbolAddress((void**)&p_kv,    g_kv);
    cudaGetSymbolAddress((void**)&p_lef,   g_lef);
    cudaGetSymbolAddress((void**)&p_qlast, g_qlast);
    cudaGetSymbolAddress((void**)&p_ctx,   g_ctx);
    cudaGetSymbolAddress((void**)&p_qh,    g_qh);
    cudaGetSymbolAddress((void**)&p_khv,   g_khv);
    cudaGetSymbolAddress((void**)&p_nb,    g_nb);
    cudaGetSymbolAddress((void**)&p_gi,    g_gi);
    cudaGetSymbolAddress((void**)&p_ipw,   g_ipw);
    cudaGetSymbolAddress((void**)&p_gwih,  g_gwih);
    cudaGetSymbolAddress((void**)&p_wkvT,  g_wkvT);
    cudaGetSymbolAddress((void**)&p_w3t,   g_w3t);
    cudaGetSymbolAddress((void**)&p_bqh,   g_bqh);

    // --- prep (gather, packing, weight conversion, W3 fusion precompute) ---
    build_kernel<<<BS*HL, 128>>>(nids, hist_nids, aids, eids, hist_ts, dirs,
                                 node_feat, edge_feat, anony_emb, time_w, time_b);
    transpose_odew<<<128, 128>>>(ode_w);
    pack_wkvT<<<384, 128>>>(attn_wk, attn_wv);
    cvt_tf32<<<(1920*640 + 255)/256, 256>>>(in_proj_w, p_ipw, 1920*640);
    cvt_tf32<<<(384*512 + 255)/256, 256>>>(gru_w_ih, p_gwih, 384*512);
    w3_step1<<<16, 128>>>(outfn_w, out_proj_w);
    w3_step2<<<16, 128>>>(attn_wq);
    w3_bias<<<1, 128>>>(out_proj_b, outfn_w, outfn_b, attn_wq);

    // --- KV projection: [81920,640] x [1280,640]^T ---
    tgemm<<<dim3(10, 640), 128>>>(DM, p_full, DM, p_ipw + (size_t)DM*DM,
                                  p_kv, 1280, in_proj_b + DM);

    // --- Q at last position: [4096,640] x [640,640]^T ---
    tgemm<<<dim3(5, 32), 128>>>(DM, p_full + (size_t)(HL-1)*DM, HL*DM,
                                p_ipw, p_qlast, DM, in_proj_b);

    // --- gi = lef @ gru_w_ih^T: [4096,512] x [384,512]^T ---
    tgemm<<<dim3(3, 32), 128>>>(DIN, p_lef, DIN, p_gwih, p_gi, 384, gru_b_ih);

    // --- kh|vh = nb @ wkvT^T: [81920,384] x [256,384]^T ---
    tgemm<<<dim3(2, 640), 128>>>(384, p_nb, 384, p_wkvT, p_khv, 256,
                                 (const float*)nullptr);

    // --- attention 1 -> ctx ---
    attn1_kernel<<<BS, 256>>>(hist_nids);

    // --- fused qh = ctx @ W3t^T: [4096,640] x [128,640]^T ---
    tgemm<<<dim3(1, 32), 128>>>(DM, p_ctx, DM, p_w3t, p_qh, NF, p_bqh);

    // --- attention 2 + merge + GRU (writes h_right + ts) ---
    attn2_gru_kernel<<<BS, 128>>>(nids, hist_nids, hist_ts, node_feat,
                                  merge_w, merge_b, gru_w_hh, gru_b_hh, out);

    // --- ODE RK4 (writes h_left) ---
    ode_kernel<<<BS, 128>>>(hist_ts, tnode_w, tnode_b, ode_b, out);
}

// round 6
// speedup vs baseline: 1.0645x; 1.0645x over previous
#include <cuda_runtime.h>
#include <cuda_bf16.h>
#include <math.h>
#include <stdint.h>

// Problem constants
#define BS 4096
#define HL 20
#define NF 128
#define EF 128
#define TF 128
#define DM 640          // 3*NF + EF + TF
#define DIN 512         // DM - TF
#define NHEAD 2
#define DH 320          // DM / NHEAD
#define ODE_STEPS 8

// K-block interleave: position 4t+i within each 16-block holds original k=t+4i.
// Writer maps original column k -> PERM(k).
#define PERM(k) (((k) & ~15) | (((k) & 3) << 2) | (((k) & 15) >> 2))

// ---------------- scratch (device globals; no allocation allowed) ----------
__device__ float g_full [(size_t)BS*HL*DM];     // full_vals (tf32, K-permuted)
__device__ float g_nb   [(size_t)BS*HL*384];    // nb (tf32, K-permuted)
__device__ float g_kv   [(size_t)BS*HL*1280];   // k|v (GEMM output, normal)
__device__ float g_lef  [(size_t)BS*DIN];       // last_event_feat (tf32, K-permuted)
__device__ float g_qlast[(size_t)BS*DM];
__device__ float g_ctx  [(size_t)BS*DM];        // (tf32, K-permuted)
__device__ float g_qh   [(size_t)BS*NF];
__device__ float g_khv  [(size_t)BS*HL*256];    // kh|vh fused (output, normal)
__device__ float g_gi   [(size_t)BS*384];
__device__ float g_hpr  [(size_t)BS*NF];
__device__ float g_odewT[NF*NF];
__device__ float g_ipw  [1920*640];             // tf32, K-permuted in_proj_w
__device__ float g_gwih [384*512];              // tf32, K-permuted gru_w_ih
__device__ float g_wkvT [256*384];              // [attn_wk|attn_wv]^T (tf32, K-perm)
__device__ float g_wq2  [128*640];              // outfn_w @ out_proj_w
__device__ float g_w3t  [128*640];              // fused qh weight (tf32, K-perm)
__device__ float g_bqh  [128];                  // fused qh bias

__device__ __forceinline__ uint32_t f2tf(float x) {
    uint32_t u; asm("cvt.rna.tf32.f32 %0, %1;" : "=r"(u) : "f"(x)); return u;
}
__device__ __forceinline__ float tfr(float x) { return __uint_as_float(f2tf(x)); }

__device__ __forceinline__ void cp16(uint32_t dst, const void* src) {
    asm volatile("cp.async.cg.shared.global [%0], [%1], 16;" :: "r"(dst), "l"(src));
}

// ---------------- TF32 mma.sync GEMM, TN form, K-interleaved operands -------
// C[M,N] = A[M,K] * B[N,K]^T + bias.  M%128==0, N%128==0, K%16==0.
// A and B stored with PERM'd K within each 16-block.
// grid = (N/128, M/128), 128 threads, 4 warps of 64x64.
__global__ __launch_bounds__(128, 2)
void tgemm(int K, const float* __restrict__ A, int lda,
           const float* __restrict__ B,
           float* __restrict__ C, int ldc,
           const float* __restrict__ bias)
{
    __shared__ float As[2][128][16];
    __shared__ float Bs[2][128][16];
    int tid = threadIdx.x;
    int warp = tid >> 5, lane = tid & 31;
    int row0 = blockIdx.y * 128, col0 = blockIdx.x * 128;
    int m0 = (warp >> 1) * 64, n0 = (warp & 1) * 64;
    int g = lane >> 2, t = lane & 3;

    float c[4][8][4];
#pragma unroll
    for (int mi = 0; mi < 4; mi++)
#pragma unroll
        for (int ni = 0; ni < 8; ni++)
#pragma unroll
            for (int i = 0; i < 4; i++) c[mi][ni][i] = 0.f;

    const float* Ap = A + (size_t)row0 * lda;
    const float* Bp = B + (size_t)col0 * K;

    uint32_t sA = (uint32_t)__cvta_generic_to_shared(&As[0][0][0]);
    uint32_t sB = (uint32_t)__cvta_generic_to_shared(&Bs[0][0][0]);
    const uint32_t stg = 128u*16u*4u;

#define LOADSTAGE(s, kt) {                                                    \
        _Pragma("unroll")                                                     \
        for (int i = 0; i < 4; i++) {                                         \
            int j = tid + i*128, r = j >> 2, q = j & 3;                       \
            cp16(sA + (s)*stg + (uint32_t)(r*16 + q*4)*4u,                    \
                 Ap + (size_t)r*lda + (kt)*16 + q*4);                         \
            cp16(sB + (s)*stg + (uint32_t)(r*16 + q*4)*4u,                    \
                 Bp + (size_t)r*K + (kt)*16 + q*4);                           \
        }                                                                     \
        asm volatile("cp.async.commit_group;" ::: "memory");                  \
    }

    int T = K >> 4;
    LOADSTAGE(0, 0);

    for (int kt = 0; kt < T; kt++) {
        int s = kt & 1;
        asm volatile("cp.async.wait_group 0;" ::: "memory");
        __syncthreads();
        if (kt + 1 < T) LOADSTAGE(s ^ 1, kt + 1);

        // one LDS.128 per fragment row/col: lanes t*16B within 64B rows
        float4 av[4][2], bv[8];
#pragma unroll
        for (int mi = 0; mi < 4; mi++) {
            int rm = m0 + mi*16 + g;
            av[mi][0] = *(const float4*)&As[s][rm    ][t*4];
            av[mi][1] = *(const float4*)&As[s][rm + 8][t*4];
        }
#pragma unroll
        for (int ni = 0; ni < 8; ni++) {
            int cn = n0 + ni*8 + g;
            bv[ni] = *(const float4*)&Bs[s][cn][t*4];
        }
#pragma unroll
        for (int mi = 0; mi < 4; mi++)
#pragma unroll
            for (int ni = 0; ni < 8; ni++) {
                asm volatile(
                    "mma.sync.aligned.m16n8k8.row.col.f32.tf32.tf32.f32 "
                    "{%0,%1,%2,%3},{%4,%5,%6,%7},{%8,%9},{%0,%1,%2,%3};\n"
                    : "+f"(c[mi][ni][0]), "+f"(c[mi][ni][1]),
                      "+f"(c[mi][ni][2]), "+f"(c[mi][ni][3])
                    : "r"(__float_as_uint(av[mi][0].x)), "r"(__float_as_uint(av[mi][1].x)),
                      "r"(__float_as_uint(av[mi][0].y)), "r"(__float_as_uint(av[mi][1].y)),
                      "r"(__float_as_uint(bv[ni].x)),    "r"(__float_as_uint(bv[ni].y)));
                asm volatile(
                    "mma.sync.aligned.m16n8k8.row.col.f32.tf32.tf32.f32 "
                    "{%0,%1,%2,%3},{%4,%5,%6,%7},{%8,%9},{%0,%1,%2,%3};\n"
                    : "+f"(c[mi][ni][0]), "+f"(c[mi][ni][1]),
                      "+f"(c[mi][ni][2]), "+f"(c[mi][ni][3])
                    : "r"(__float_as_uint(av[mi][0].z)), "r"(__float_as_uint(av[mi][1].z)),
                      "r"(__float_as_uint(av[mi][0].w)), "r"(__float_as_uint(av[mi][1].w)),
                      "r"(__float_as_uint(bv[ni].z)),    "r"(__float_as_uint(bv[ni].w)));
            }
        __syncthreads();
    }

#pragma unroll
    for (int mi = 0; mi < 4; mi++) {
        size_t r1 = (size_t)(row0 + m0 + mi*16 + g);
        size_t r2 = r1 + 8;
#pragma unroll
        for (int ni = 0; ni < 8; ni++) {
            int cc = col0 + n0 + ni*8 + 2*t;
            float b0 = 0.f, b1 = 0.f;
            if (bias) { b0 = bias[cc]; b1 = bias[cc + 1]; }
            *(float2*)&C[r1*ldc + cc] = make_float2(c[mi][ni][0] + b0, c[mi][ni][1] + b1);
            *(float2*)&C[r2*ldc + cc] = make_float2(c[mi][ni][2] + b0, c[mi][ni][3] + b1);
        }
    }
#undef LOADSTAGE
}

// ---------------- build full_vals, nb, last_event_feat (tf32 + K-perm) -----
__global__ void build_kernel(const int* __restrict__ nids,
                             const int* __restrict__ hist_nids,
                             const int* __restrict__ aids,
                             const int* __restrict__ eids,
                             const float* __restrict__ hist_ts,
                             const int* __restrict__ dirs,
                             const float* __restrict__ node_feat,
                             const float* __restrict__ edge_feat,
                             const float* __restrict__ anony,
                             const float* __restrict__ tw,
                             const float* __restrict__ tb)
{
    int bl = blockIdx.x;            // b*HL + l
    int b  = bl / HL, l = bl % HL;
    int j  = threadIdx.x;           // 0..127
    int jp = PERM(j);               // permuted within-section index
    int hn  = hist_nids[bl];
    int dir = dirs[bl];
    int nid = nids[b];
    int src = dir ? nid : hn;
    int dst = dir ? hn  : nid;
    float sv = tfr(node_feat[(size_t)src*NF + j]);
    float dv = tfr(node_feat[(size_t)dst*NF + j]);
    float av = tfr(anony[(size_t)aids[bl]*NF + j]);
    float ev = tfr(edge_feat[(size_t)eids[bl]*EF + j]);
    float dt = hist_ts[b*HL + HL-1] - hist_ts[bl];
    float tv = tfr(cosf(dt*tw[j] + tb[j]));

    float* fv = g_full + (size_t)bl*DM;
    if (l == HL-1) {
        float* lef = g_lef + (size_t)b*DIN;
        lef[jp] = sv; lef[NF+jp] = dv; lef[2*NF+jp] = av; lef[3*NF+jp] = ev;
        fv[jp] = 0.f; fv[NF+jp] = 0.f; fv[2*NF+jp] = 0.f; fv[3*NF+jp] = 0.f;
        fv[4*NF+jp] = tv;
    } else {
        fv[jp] = sv; fv[NF+jp] = dv; fv[2*NF+jp] = av; fv[3*NF+jp] = ev;
        fv[4*NF+jp] = tv;
    }
    float* nb = g_nb + (size_t)bl*384;
    nb[jp]        = tfr(node_feat[(size_t)hn*NF + j]);
    nb[NF + jp]   = ev;
    nb[2*NF + jp] = tv;
}

__global__ void transpose_odew(const float* __restrict__ w)
{
    int idx = blockIdx.x*128 + threadIdx.x;
    int j = idx >> 7, k = idx & 127;
    g_odewT[k*NF + j] = w[idx];
}

__global__ void pack_wkvT(const float* __restrict__ wk, const float* __restrict__ wv)
{
    int idx = blockIdx.x*128 + threadIdx.x;   // 384*128
    int k = idx >> 7, n = idx & 127;
    int kp = PERM(k);
    g_wkvT[(size_t)n*384 + kp]         = tfr(wk[idx]);
    g_wkvT[(size_t)(128 + n)*384 + kp] = tfr(wv[idx]);
}

// tf32-round + K-permute columns of a row-major [rows, K] matrix
__global__ void cvt_tf32p(const float* __restrict__ s, float* __restrict__ d,
                          int K, int n)
{
    int i = blockIdx.x*256 + threadIdx.x;
    if (i < n) {
        int row = i / K, col = i % K;
        d[(size_t)row*K + PERM(col)] = tfr(s[i]);
    }
}

// W3 precompute: Wq2 = outfn_w @ out_proj_w  ([128,640])
__global__ void w3_step1(const float* __restrict__ outfn_w, const float* __restrict__ opw)
{
    __shared__ float srow[8][640];
    int i0 = blockIdx.x * 8;    // grid 16
    for (int j = threadIdx.x; j < 8*640; j += 128)
        srow[j/640][j%640] = outfn_w[(size_t)(i0 + j/640)*640 + (j%640)];
    __syncthreads();
    for (int t = 0; t < 5; t++) {
        int d = threadIdx.x + t*128;
        float acc[8] = {0,0,0,0,0,0,0,0};
        for (int k = 0; k < 640; k++) {
            float w = opw[(size_t)k*640 + d];
#pragma unroll
            for (int r = 0; r < 8; r++) acc[r] += srow[r][k]*w;
        }
        for (int r = 0; r < 8; r++) g_wq2[(size_t)(i0+r)*640 + d] = acc[r];
    }
}
// W3t[j,PERM(d)] = sum_i Wq2[i,d] * attn_wq[i,j]
__global__ void w3_step2(const float* __restrict__ attn_wq)
{
    __shared__ float wqc[8][128];
    int j0 = blockIdx.x * 8;    // grid 16
    for (int idx = threadIdx.x; idx < 8*128; idx += 128) {
        int r = idx >> 7, i = idx & 127;
        wqc[r][i] = attn_wq[(size_t)i*128 + j0 + r];
    }
    __syncthreads();
    for (int t = 0; t < 5; t++) {
        int d = threadIdx.x + t*128;
        int dp = PERM(d);
        float acc[8] = {0,0,0,0,0,0,0,0};
        for (int i = 0; i < 128; i++) {
            float w = g_wq2[(size_t)i*640 + d];
#pragma unroll
            for (int r = 0; r < 8; r++) acc[r] += wqc[r][i]*w;
        }
        for (int r = 0; r < 8; r++) g_w3t[(size_t)(j0+r)*640 + dp] = tfr(acc[r]);
    }
}
// bqh[j] = sum_i (outfn_b[i] + sum_k out_proj_b[k]*outfn_w[i,k]) * attn_wq[i,j]
__global__ void w3_bias(const float* __restrict__ opb, const float* __restrict__ outfn_w,
                        const float* __restrict__ outfn_b, const float* __restrict__ attn_wq)
{
    __shared__ float bq2[128];
    int i = threadIdx.x;
    float a = outfn_b[i];
    for (int k = 0; k < 640; k++) a += opb[k]*outfn_w[(size_t)i*640 + k];
    bq2[i] = a;
    __syncthreads();
    float s = 0.f;
    for (int ii = 0; ii < 128; ii++) s += bq2[ii]*attn_wq[(size_t)ii*128 + i];
    g_bqh[i] = s;
}

// ---------------- attention 1 (query = last position) ----------------------
__global__ void attn1_kernel(const int* __restrict__ hist_nids)
{
    int b = blockIdx.x, tid = threadIdx.x;   // 256 threads
    __shared__ float sq[DM];
    __shared__ float sS[NHEAD*HL];
    __shared__ float sA[NHEAD*HL];
    for (int d = tid; d < DM; d += 256) sq[d] = g_qlast[(size_t)b*DM + d];
    __syncthreads();

    int warp = tid >> 5, lane = tid & 31;
    for (int p = warp; p < NHEAD*HL; p += 8) {
        int h = p / HL, m = p % HL;
        const float* krow = g_kv + (size_t)(b*HL + m)*1280 + h*DH;
        const float* qrow = sq + h*DH;
        float s = 0.f;
#pragma unroll
        for (int i = 0; i < 10; i++) { int d = lane + i*32; s += qrow[d]*krow[d]; }
#pragma unroll
        for (int o = 16; o; o >>= 1) s += __shfl_xor_sync(0xffffffffu, s, o);
        if (!lane) sS[p] = s * 0.05590169943749474f;   // 1/sqrt(320)
    }
    __syncthreads();
    if (tid < NHEAD) {
        int h = tid;
        float sc[HL], mx = -1e30f;
        for (int m = 0; m < HL; m++) {
            float v = sS[h*HL + m];
            if (hist_nids[b*HL + m] == 0 && m != HL-1) v = -1e9f;
            sc[m] = v; mx = fmaxf(mx, v);
        }
        float sum = 0.f;
        for (int m = 0; m < HL; m++) { float e = expf(sc[m]-mx); sc[m] = e; sum += e; }
        float inv = 1.f/sum;
        for (int m = 0; m < HL; m++) sA[h*HL + m] = sc[m]*inv;
    }
    __syncthreads();
    for (int d = tid; d < DM; d += 256) {
        int h = d / DH;
        const float* vbase = g_kv + (size_t)b*HL*1280 + 640 + d;
        float accv = 0.f;
#pragma unroll
        for (int m = 0; m < HL; m++) accv += sA[h*HL + m] * vbase[(size_t)m*1280];
        g_ctx[(size_t)b*DM + PERM(d)] = tfr(accv);   // K-permuted: feeds qh GEMM
    }
}

// ---------------- attention 2 + merge + GRU ---------------------------------
__global__ void attn2_gru_kernel(const int* __restrict__ nids,
                                 const int* __restrict__ hist_nids,
                                 const float* __restrict__ hist_ts,
                                 const float* __restrict__ node_feat,
                                 const float* __restrict__ merge_w,
                                 const float* __restrict__ merge_b,
                                 const float* __restrict__ gwhh,
                                 const float* __restrict__ gbhh,
                                 float* __restrict__ out)
{
    int b = blockIdx.x, tid = threadIdx.x;   // 128 threads
    __shared__ float sqh[NF], ssc[HL], sa[HL], scat[2*NF], shpl[NF];
    sqh[tid] = g_qh[(size_t)b*NF + tid];
    __syncthreads();
    int warp = tid >> 5, lane = tid & 31;
    for (int l = warp; l < HL; l += 4) {
        const float* kr = g_khv + (size_t)(b*HL + l)*256;
        float s = 0.f;
#pragma unroll
        for (int i = 0; i < 4; i++) { int d = lane + i*32; s += sqh[d]*kr[d]; }
#pragma unroll
        for (int o = 16; o; o >>= 1) s += __shfl_xor_sync(0xffffffffu, s, o);
        if (!lane) ssc[l] = s * 0.08838834764831845f;  // 1/sqrt(128)
    }
    __syncthreads();
    if (tid == 0) {
        float sc[HL], mx = -1e30f;
        for (int l = 0; l < HL; l++) {
            float v = ssc[l];
            if (hist_nids[b*HL + l] == 0 && l != HL-1) v = -1e9f;
            sc[l] = v; mx = fmaxf(mx, v);
        }
        float sum = 0.f;
        for (int l = 0; l < HL; l++) { float e = expf(sc[l]-mx); sc[l] = e; sum += e; }
        float inv = 1.f/sum;
        for (int l = 0; l < HL; l++) sa[l] = sc[l]*inv;
    }
    __syncthreads();
    float c2 = 0.f;
#pragma unroll
    for (int l = 0; l < HL; l++) c2 += sa[l] * g_khv[(size_t)(b*HL + l)*256 + 128 + tid];
    scat[tid]      = c2;
    scat[NF + tid] = node_feat[(size_t)nids[b]*NF + tid];
    __syncthreads();

    float acc = merge_b[tid];
#pragma unroll 8
    for (int k = 0; k < 2*NF; k++) acc = fmaf(scat[k], merge_w[k*NF + tid], acc);
    float hpl = tanhf(acc);
    shpl[tid] = hpl;
    __syncthreads();

    float gh[3];
#pragma unroll
    for (int c = 0; c < 3; c++) {
        int i = c*NF + tid;
        float a = gbhh[i];
        const float* wrow = gwhh + (size_t)i*NF;
#pragma unroll 8
        for (int k = 0; k < NF; k++) a = fmaf(shpl[k], wrow[k], a);
        gh[c] = a;
    }
    const float* gi = g_gi + (size_t)b*384;
    float r = 1.f/(1.f + expf(-(gi[tid]       + gh[0])));
    float z = 1.f/(1.f + expf(-(gi[NF + tid]  + gh[1])));
    float n = tanhf(gi[2*NF + tid] + r*gh[2]);
    float hpr = (1.f - z)*n + z*hpl;
    g_hpr[(size_t)b*NF + tid] = hpr;
    out[(size_t)BS*NF + (size_t)b*NF + tid] = hpr;        // h_right
    if (tid == 0) out[(size_t)2*BS*NF + b] = hist_ts[b*HL + HL-1];
}

// ---------------- ODE (RK4, 8 steps), 8 samples/block, weights in smem ------
__global__ __launch_bounds__(128)
void ode_kernel(const float* __restrict__ hist_ts,
                const float* __restrict__ tnw,
                const float* __restrict__ tnb,
                const float* __restrict__ odeb,
                float* __restrict__ out)
{
    extern __shared__ float sm[];           // wsm[16384] + ysm[128*8]
    float* wsm = sm;
    float* ysm = sm + NF*NF;
    int j = threadIdx.x;
    int b0 = blockIdx.x * 8;

    for (int i = j; i < NF*NF; i += 128) wsm[i] = g_odewT[i];
    float tw = tnw[j], tb = tnb[j], ob = odeb[j];
    float t0v[8], rat[8], z[8];
#pragma unroll
    for (int s = 0; s < 8; s++) {
        float a = hist_ts[(b0+s)*HL + HL-2];
        float b = hist_ts[(b0+s)*HL + HL-1];
        t0v[s] = a; rat[s] = b - a;
        z[s] = g_hpr[(size_t)(b0+s)*NF + j];
    }
    __syncthreads();
    const float ds = 1.f/ODE_STEPS;

    auto fstage = [&](float sfrac, const float* zi, float* f) {
        __syncthreads();   // WAR: previous reads of ysm done
#pragma unroll
        for (int s = 0; s < 8; s++) {
            float te = __cosf((sfrac*rat[s] + t0v[s])*tw + tb);
            ysm[j*8 + s] = zi[s] + te;
        }
        __syncthreads();
        float acc[8];
#pragma unroll
        for (int s = 0; s < 8; s++) acc[s] = ob;
#pragma unroll 4
        for (int k = 0; k < NF; k++) {
            float w = wsm[k*NF + j];
            float4 y0 = *(const float4*)&ysm[k*8];
            float4 y1 = *(const float4*)&ysm[k*8 + 4];
            acc[0] = fmaf(y0.x, w, acc[0]);
            acc[1] = fmaf(y0.y, w, acc[1]);
            acc[2] = fmaf(y0.z, w, acc[2]);
            acc[3] = fmaf(y0.w, w, acc[3]);
            acc[4] = fmaf(y1.x, w, acc[4]);
            acc[5] = fmaf(y1.y, w, acc[5]);
            acc[6] = fmaf(y1.z, w, acc[6]);
            acc[7] = fmaf(y1.w, w, acc[7]);
        }
#pragma unroll
        for (int s = 0; s < 8; s++) {
            float th;
            asm("tanh.approx.f32 %0, %1;" : "=f"(th) : "f"(acc[s]));
            f[s] = th * rat[s];
        }
    };

    for (int i = 0; i < ODE_STEPS; i++) {
        float s0 = i * ds;
        float k1[8], k2[8], k3[8], k4[8], zi[8];
        fstage(s0, z, k1);
#pragma unroll
        for (int s = 0; s < 8; s++) zi[s] = z[s] + 0.5f*ds*k1[s];
        fstage(s0 + 0.5f*ds, zi, k2);
#pragma unroll
        for (int s = 0; s < 8; s++) zi[s] = z[s] + 0.5f*ds*k2[s];
        fstage(s0 + 0.5f*ds, zi, k3);
#pragma unroll
        for (int s = 0; s < 8; s++) zi[s] = z[s] + ds*k3[s];
        fstage(s0 + ds, zi, k4);
#pragma unroll
        for (int s = 0; s < 8; s++)
            z[s] += ds/6.f * (k1[s] + 2.f*k2[s] + 2.f*k3[s] + k4[s]);
    }
#pragma unroll
    for (int s = 0; s < 8; s++)
        out[(size_t)(b0+s)*NF + j] = z[s];   // h_left
}

// ---------------- host ------------------------------------------------------
extern "C" void kernel_launch(void* const* d_in, const int* in_sizes, int n_in,
                              void* d_out, int out_size)
{
    const int*   nids       = (const int*)  d_in[0];
    const int*   hist_nids  = (const int*)  d_in[2];
    const int*   aids       = (const int*)  d_in[3];
    const int*   eids       = (const int*)  d_in[4];
    const float* hist_ts    = (const float*)d_in[5];
    const int*   dirs       = (const int*)  d_in[6];
    const float* node_feat  = (const float*)d_in[7];
    const float* edge_feat  = (const float*)d_in[8];
    const float* anony_emb  = (const float*)d_in[9];
    const float* time_w     = (const float*)d_in[10];
    const float* time_b     = (const float*)d_in[11];
    const float* in_proj_w  = (const float*)d_in[12];
    const float* in_proj_b  = (const float*)d_in[13];
    const float* out_proj_w = (const float*)d_in[14];
    const float* out_proj_b = (const float*)d_in[15];
    const float* outfn_w    = (const float*)d_in[16];
    const float* outfn_b    = (const float*)d_in[17];
    const float* attn_wq    = (const float*)d_in[18];
    const float* attn_wk    = (const float*)d_in[19];
    const float* attn_wv    = (const float*)d_in[20];
    const float* merge_w    = (const float*)d_in[21];
    const float* merge_b    = (const float*)d_in[22];
    const float* gru_w_ih   = (const float*)d_in[23];
    const float* gru_w_hh   = (const float*)d_in[24];
    const float* gru_b_ih   = (const float*)d_in[25];
    const float* gru_b_hh   = (const float*)d_in[26];
    const float* ode_w      = (const float*)d_in[27];
    const float* ode_b      = (const float*)d_in[28];
    const float* tnode_w    = (const float*)d_in[29];
    const float* tnode_b    = (const float*)d_in[30];

    float* out = (float*)d_out;

    float *p_full, *p_kv, *p_lef, *p_qlast, *p_ctx, *p_qh, *p_khv, *p_nb,
          *p_gi, *p_ipw, *p_gwih, *p_wkvT, *p_w3t, *p_bqh;
    cudaGetSymbolAddress((void**)&p_full,  g_full);
    cudaGetSymbolAddress((void**)&p_kv,    g_kv);
    cudaGetSymbolAddress((void**)&p_lef,   g_lef);
    cudaGetSymbolAddress((void**)&p_qlast, g_qlast);
    cudaGetSymbolAddress((void**)&p_ctx,   g_ctx);
    cudaGetSymbolAddress((void**)&p_qh,    g_qh);
    cudaGetSymbolAddress((void**)&p_khv,   g_khv);
    cudaGetSymbolAddress((void**)&p_nb,    g_nb);
    cudaGetSymbolAddress((void**)&p_gi,    g_gi);
    cudaGetSymbolAddress((void**)&p_ipw,   g_ipw);
    cudaGetSymbolAddress((void**)&p_gwih,  g_gwih);
    cudaGetSymbolAddress((void**)&p_wkvT,  g_wkvT);
    cudaGetSymbolAddress((void**)&p_w3t,   g_w3t);
    cudaGetSymbolAddress((void**)&p_bqh,   g_bqh);

    // ODE needs 69.6KB dynamic smem (> 48KB default): opt in (idempotent)
    cudaFuncSetAttribute(ode_kernel, cudaFuncAttributeMaxDynamicSharedMemorySize,
                         (NF*NF + NF*8) * 4);

    // --- prep (gather, packing, weight conversion, W3 fusion precompute) ---
    build_kernel<<<BS*HL, 128>>>(nids, hist_nids, aids, eids, hist_ts, dirs,
                                 node_feat, edge_feat, anony_emb, time_w, time_b);
    transpose_odew<<<128, 128>>>(ode_w);
    pack_wkvT<<<384, 128>>>(attn_wk, attn_wv);
    cvt_tf32p<<<(1920*640 + 255)/256, 256>>>(in_proj_w, p_ipw, 640, 1920*640);
    cvt_tf32p<<<(384*512 + 255)/256, 256>>>(gru_w_ih, p_gwih, 512, 384*512);
    w3_step1<<<16, 128>>>(outfn_w, out_proj_w);
    w3_step2<<<16, 128>>>(attn_wq);
    w3_bias<<<1, 128>>>(out_proj_b, outfn_w, outfn_b, attn_wq);

    // --- KV projection: [81920,640] x [1280,640]^T ---
    tgemm<<<dim3(10, 640), 128>>>(DM, p_full, DM, p_ipw + (size_t)DM*DM,
                                  p_kv, 1280, in_proj_b + DM);

    // --- Q at last position: [4096,640] x [640,640]^T ---
    tgemm<<<dim3(5, 32), 128>>>(DM, p_full + (size_t)(HL-1)*DM, HL*DM,
                                p_ipw, p_qlast, DM, in_proj_b);

    // --- gi = lef @ gru_w_ih^T: [4096,512] x [384,512]^T ---
    tgemm<<<dim3(3, 32), 128>>>(DIN, p_lef, DIN, p_gwih, p_gi, 384, gru_b_ih);

    // --- kh|vh = nb @ wkvT^T: [81920,384] x [256,384]^T ---
    tgemm<<<dim3(2, 640), 128>>>(384, p_nb, 384, p_wkvT, p_khv, 256,
                                 (const float*)nullptr);

    // --- attention 1 -> ctx ---
    attn1_kernel<<<BS, 256>>>(hist_nids);

    // --- fused qh = ctx @ W3t^T: [4096,640] x [128,640]^T ---
    tgemm<<<dim3(1, 32), 128>>>(DM, p_ctx, DM, p_w3t, p_qh, NF, p_bqh);

    // --- attention 2 + merge + GRU (writes h_right + ts) ---
    attn2_gru_kernel<<<BS, 128>>>(nids, hist_nids, hist_ts, node_feat,
                                  merge_w, merge_b, gru_w_hh, gru_b_hh, out);

    // --- ODE RK4 (writes h_left) ---
    ode_kernel<<<BS/8, 128, (NF*NF + NF*8)*4>>>(hist_ts, tnode_w, tnode_b,
                                                ode_b, out);
}